// round 3
// baseline (speedup 1.0000x reference)
#include <cuda_runtime.h>
#include <math.h>

#define B_    8
#define CIN_  512
#define COUT_ 3
#define HW_   65536   // 256*256
#define ZDIM_ 512

// Final demodulated weights, padded float4 per ci: (w0,w1,w2,0). [B][CIN]
__device__ float4 g_ww4[B_ * CIN_];

// ---------------------------------------------------------------------------
// Kernel 1: full style pipeline in one block per batch.
// grid=(B), block=1024 = 128 ci4-lanes (4 ci each) x 8 z-slices (64 z each).
// ---------------------------------------------------------------------------
__global__ __launch_bounds__(1024) void style_kernel(const float* __restrict__ y,
                                                     const float* __restrict__ w,
                                                     const float* __restrict__ dense_w,
                                                     const float* __restrict__ dense_b) {
    const int b    = blockIdx.x;
    const int tid  = threadIdx.x;
    const int ci4  = tid & 127;     // handles ci = ci4*4 .. ci4*4+3
    const int zs   = tid >> 7;      // 0..7, z in [zs*64, zs*64+64)

    __shared__ float  sy[ZDIM_];
    __shared__ float4 sred[8][128];  // [zslice][ci4]
    __shared__ float  swq[4][3];     // per-warp square partials (warps 0..3)
    __shared__ float  sdq[3];        // final demod sums

    if (tid < ZDIM_) sy[tid] = y[b * ZDIM_ + tid];
    __syncthreads();

    // partial dot over 64 z for 4 consecutive ci (float4 loads of dense_w)
    const float4* dw4 = reinterpret_cast<const float4*>(dense_w);
    float4 acc = make_float4(0.f, 0.f, 0.f, 0.f);
    const int z0 = zs * 64;
#pragma unroll 16
    for (int zz = 0; zz < 64; ++zz) {
        const int z = z0 + zz;
        const float  yv = sy[z];
        const float4 dv = dw4[z * 128 + ci4];
        acc.x = fmaf(yv, dv.x, acc.x);
        acc.y = fmaf(yv, dv.y, acc.y);
        acc.z = fmaf(yv, dv.z, acc.z);
        acc.w = fmaf(yv, dv.w, acc.w);
    }
    sred[zs][ci4] = acc;
    __syncthreads();

    float ww[4][3];  // only valid on tid < 128
    if (tid < 128) {
        float4 dot = sred[0][ci4];
#pragma unroll
        for (int k = 1; k < 8; ++k) {
            const float4 v = sred[k][ci4];
            dot.x += v.x; dot.y += v.y; dot.z += v.z; dot.w += v.w;
        }
        const float rc = 0.044194173824159216f;   // 1/sqrt(512)
        const int   ci0 = ci4 * 4;
        const float s[4] = {
            dot.x * rc + dense_b[ci0 + 0] + 1.0f,
            dot.y * rc + dense_b[ci0 + 1] + 1.0f,
            dot.z * rc + dense_b[ci0 + 2] + 1.0f,
            dot.w * rc + dense_b[ci0 + 3] + 1.0f };

        float q0 = 0.f, q1 = 0.f, q2 = 0.f;
#pragma unroll
        for (int j = 0; j < 4; ++j) {
            const float* wp = w + (ci0 + j) * COUT_;
            ww[j][0] = rc * wp[0] * s[j];
            ww[j][1] = rc * wp[1] * s[j];
            ww[j][2] = rc * wp[2] * s[j];
            q0 += ww[j][0] * ww[j][0];
            q1 += ww[j][1] * ww[j][1];
            q2 += ww[j][2] * ww[j][2];
        }
#pragma unroll
        for (int off = 16; off >= 1; off >>= 1) {
            q0 += __shfl_xor_sync(0xFFFFFFFF, q0, off);
            q1 += __shfl_xor_sync(0xFFFFFFFF, q1, off);
            q2 += __shfl_xor_sync(0xFFFFFFFF, q2, off);
        }
        const int warp = ci4 >> 5;
        if ((ci4 & 31) == 0) {
            swq[warp][0] = q0; swq[warp][1] = q1; swq[warp][2] = q2;
        }
    }
    __syncthreads();
    if (tid < 3)
        sdq[tid] = swq[0][tid] + swq[1][tid] + swq[2][tid] + swq[3][tid];
    __syncthreads();

    if (tid < 128) {
        const float d0 = rsqrtf(sdq[0] + 1e-8f);
        const float d1 = rsqrtf(sdq[1] + 1e-8f);
        const float d2 = rsqrtf(sdq[2] + 1e-8f);
        const int ci0 = ci4 * 4;
#pragma unroll
        for (int j = 0; j < 4; ++j)
            g_ww4[b * CIN_ + ci0 + j] =
                make_float4(ww[j][0] * d0, ww[j][1] * d1, ww[j][2] * d2, 0.f);
    }
}

// ---------------------------------------------------------------------------
// Kernel 2: pointwise conv, HBM streaming. grid=(128, B), block=128.
// ---------------------------------------------------------------------------
__global__ __launch_bounds__(128) void conv_kernel(const float* __restrict__ x,
                                                   float* __restrict__ out) {
    const int b    = blockIdx.y;
    const int pix4 = blockIdx.x * 128 + threadIdx.x;  // 0 .. HW/4-1

    __shared__ float4 sw[CIN_];
    for (int i = threadIdx.x; i < CIN_; i += 128)
        sw[i] = g_ww4[b * CIN_ + i];
    __syncthreads();

    const float4* xb = reinterpret_cast<const float4*>(
                           x + (size_t)b * CIN_ * HW_) + pix4;

    float4 a0 = make_float4(0.f, 0.f, 0.f, 0.f);
    float4 a1 = make_float4(0.f, 0.f, 0.f, 0.f);
    float4 a2 = make_float4(0.f, 0.f, 0.f, 0.f);

#pragma unroll 8
    for (int ci = 0; ci < CIN_; ++ci) {
        const float4 v  = __ldcs(&xb[(size_t)ci * (HW_ / 4)]);
        const float4 wv = sw[ci];
        a0.x = fmaf(wv.x, v.x, a0.x); a0.y = fmaf(wv.x, v.y, a0.y);
        a0.z = fmaf(wv.x, v.z, a0.z); a0.w = fmaf(wv.x, v.w, a0.w);
        a1.x = fmaf(wv.y, v.x, a1.x); a1.y = fmaf(wv.y, v.y, a1.y);
        a1.z = fmaf(wv.y, v.z, a1.z); a1.w = fmaf(wv.y, v.w, a1.w);
        a2.x = fmaf(wv.z, v.x, a2.x); a2.y = fmaf(wv.z, v.y, a2.y);
        a2.z = fmaf(wv.z, v.z, a2.z); a2.w = fmaf(wv.z, v.w, a2.w);
    }

    float4* ob = reinterpret_cast<float4*>(out + (size_t)b * COUT_ * HW_);
    __stcs(&ob[0 * (HW_ / 4) + pix4], a0);
    __stcs(&ob[1 * (HW_ / 4) + pix4], a1);
    __stcs(&ob[2 * (HW_ / 4) + pix4], a2);
}

// ---------------------------------------------------------------------------
// Inputs: x, y, w, dense_w, dense_b. Output: float [8,3,256,256]
// ---------------------------------------------------------------------------
extern "C" void kernel_launch(void* const* d_in, const int* in_sizes, int n_in,
                              void* d_out, int out_size) {
    const float* x       = (const float*)d_in[0];
    const float* y       = (const float*)d_in[1];
    const float* w       = (const float*)d_in[2];
    const float* dense_w = (const float*)d_in[3];
    const float* dense_b = (const float*)d_in[4];
    float* out = (float*)d_out;

    style_kernel<<<B_, 1024>>>(y, w, dense_w, dense_b);

    dim3 cgrid(HW_ / 4 / 128, B_);
    conv_kernel<<<cgrid, 128>>>(x, out);
}

// round 4
// speedup vs baseline: 1.1794x; 1.1794x over previous
#include <cuda_runtime.h>
#include <math.h>

#define B_    8
#define CIN_  512
#define COUT_ 3
#define HW_   65536   // 256*256
#define ZDIM_ 512

// Final demodulated weights, padded float4 per ci: (w0,w1,w2,0). [B][CIN]
__device__ float4 g_ww4[B_ * CIN_];

// ---------------------------------------------------------------------------
// Kernel 1: full style pipeline in one block per batch.
// grid=(B), block=1024 = 128 ci4-lanes (4 ci each) x 8 z-slices (64 z each).
// ---------------------------------------------------------------------------
__global__ __launch_bounds__(1024) void style_kernel(const float* __restrict__ y,
                                                     const float* __restrict__ w,
                                                     const float* __restrict__ dense_w,
                                                     const float* __restrict__ dense_b) {
    const int b    = blockIdx.x;
    const int tid  = threadIdx.x;
    const int ci4  = tid & 127;     // handles ci = ci4*4 .. ci4*4+3
    const int zs   = tid >> 7;      // 0..7, z in [zs*64, zs*64+64)

    __shared__ float  sy[ZDIM_];
    __shared__ float4 sred[8][128];  // [zslice][ci4]
    __shared__ float  swq[4][3];     // per-warp square partials (warps 0..3)
    __shared__ float  sdq[3];        // final demod sums

    if (tid < ZDIM_) sy[tid] = y[b * ZDIM_ + tid];
    __syncthreads();

    // partial dot over 64 z for 4 consecutive ci (float4 loads of dense_w)
    const float4* dw4 = reinterpret_cast<const float4*>(dense_w);
    float4 acc = make_float4(0.f, 0.f, 0.f, 0.f);
    const int z0 = zs * 64;
#pragma unroll 16
    for (int zz = 0; zz < 64; ++zz) {
        const int z = z0 + zz;
        const float  yv = sy[z];
        const float4 dv = dw4[z * 128 + ci4];
        acc.x = fmaf(yv, dv.x, acc.x);
        acc.y = fmaf(yv, dv.y, acc.y);
        acc.z = fmaf(yv, dv.z, acc.z);
        acc.w = fmaf(yv, dv.w, acc.w);
    }
    sred[zs][ci4] = acc;
    __syncthreads();

    float ww[4][3];  // only valid on tid < 128
    if (tid < 128) {
        float4 dot = sred[0][ci4];
#pragma unroll
        for (int k = 1; k < 8; ++k) {
            const float4 v = sred[k][ci4];
            dot.x += v.x; dot.y += v.y; dot.z += v.z; dot.w += v.w;
        }
        const float rc = 0.044194173824159216f;   // 1/sqrt(512)
        const int   ci0 = ci4 * 4;
        const float s[4] = {
            dot.x * rc + dense_b[ci0 + 0] + 1.0f,
            dot.y * rc + dense_b[ci0 + 1] + 1.0f,
            dot.z * rc + dense_b[ci0 + 2] + 1.0f,
            dot.w * rc + dense_b[ci0 + 3] + 1.0f };

        float q0 = 0.f, q1 = 0.f, q2 = 0.f;
#pragma unroll
        for (int j = 0; j < 4; ++j) {
            const float* wp = w + (ci0 + j) * COUT_;
            ww[j][0] = rc * wp[0] * s[j];
            ww[j][1] = rc * wp[1] * s[j];
            ww[j][2] = rc * wp[2] * s[j];
            q0 += ww[j][0] * ww[j][0];
            q1 += ww[j][1] * ww[j][1];
            q2 += ww[j][2] * ww[j][2];
        }
#pragma unroll
        for (int off = 16; off >= 1; off >>= 1) {
            q0 += __shfl_xor_sync(0xFFFFFFFF, q0, off);
            q1 += __shfl_xor_sync(0xFFFFFFFF, q1, off);
            q2 += __shfl_xor_sync(0xFFFFFFFF, q2, off);
        }
        const int warp = ci4 >> 5;
        if ((ci4 & 31) == 0) {
            swq[warp][0] = q0; swq[warp][1] = q1; swq[warp][2] = q2;
        }
    }
    __syncthreads();
    if (tid < 3)
        sdq[tid] = swq[0][tid] + swq[1][tid] + swq[2][tid] + swq[3][tid];
    __syncthreads();

    if (tid < 128) {
        const float d0 = rsqrtf(sdq[0] + 1e-8f);
        const float d1 = rsqrtf(sdq[1] + 1e-8f);
        const float d2 = rsqrtf(sdq[2] + 1e-8f);
        const int ci0 = ci4 * 4;
#pragma unroll
        for (int j = 0; j < 4; ++j)
            g_ww4[b * CIN_ + ci0 + j] =
                make_float4(ww[j][0] * d0, ww[j][1] * d1, ww[j][2] * d2, 0.f);
    }
}

// ---------------------------------------------------------------------------
// Kernel 2: pointwise conv, HBM streaming. grid=(128, B), block=128.
// EXACT R2 inner-loop structure (plain loads/stores, scalar smem arrays),
// which measured 164.7us @ 6.54 TB/s.
// ---------------------------------------------------------------------------
__global__ __launch_bounds__(128) void conv_kernel(const float* __restrict__ x,
                                                   float* __restrict__ out) {
    const int b    = blockIdx.y;
    const int pix4 = blockIdx.x * 128 + threadIdx.x;  // 0 .. HW/4-1

    __shared__ float sw0[CIN_], sw1[CIN_], sw2[CIN_];
    for (int i = threadIdx.x; i < CIN_; i += 128) {
        const float4 wv = g_ww4[b * CIN_ + i];
        sw0[i] = wv.x; sw1[i] = wv.y; sw2[i] = wv.z;
    }
    __syncthreads();

    const float4* xb = reinterpret_cast<const float4*>(
                           x + (size_t)b * CIN_ * HW_) + pix4;

    float4 a0 = make_float4(0.f, 0.f, 0.f, 0.f);
    float4 a1 = make_float4(0.f, 0.f, 0.f, 0.f);
    float4 a2 = make_float4(0.f, 0.f, 0.f, 0.f);

#pragma unroll 8
    for (int ci = 0; ci < CIN_; ++ci) {
        const float4 v  = xb[(size_t)ci * (HW_ / 4)];
        const float  w0 = sw0[ci];
        const float  w1 = sw1[ci];
        const float  w2 = sw2[ci];
        a0.x = fmaf(w0, v.x, a0.x); a0.y = fmaf(w0, v.y, a0.y);
        a0.z = fmaf(w0, v.z, a0.z); a0.w = fmaf(w0, v.w, a0.w);
        a1.x = fmaf(w1, v.x, a1.x); a1.y = fmaf(w1, v.y, a1.y);
        a1.z = fmaf(w1, v.z, a1.z); a1.w = fmaf(w1, v.w, a1.w);
        a2.x = fmaf(w2, v.x, a2.x); a2.y = fmaf(w2, v.y, a2.y);
        a2.z = fmaf(w2, v.z, a2.z); a2.w = fmaf(w2, v.w, a2.w);
    }

    float4* ob = reinterpret_cast<float4*>(out + (size_t)b * COUT_ * HW_);
    ob[0 * (HW_ / 4) + pix4] = a0;
    ob[1 * (HW_ / 4) + pix4] = a1;
    ob[2 * (HW_ / 4) + pix4] = a2;
}

// ---------------------------------------------------------------------------
// Inputs: x, y, w, dense_w, dense_b. Output: float [8,3,256,256]
// ---------------------------------------------------------------------------
extern "C" void kernel_launch(void* const* d_in, const int* in_sizes, int n_in,
                              void* d_out, int out_size) {
    const float* x       = (const float*)d_in[0];
    const float* y       = (const float*)d_in[1];
    const float* w       = (const float*)d_in[2];
    const float* dense_w = (const float*)d_in[3];
    const float* dense_b = (const float*)d_in[4];
    float* out = (float*)d_out;

    style_kernel<<<B_, 1024>>>(y, w, dense_w, dense_b);

    dim3 cgrid(HW_ / 4 / 128, B_);
    conv_kernel<<<cgrid, 128>>>(x, out);
}

// round 5
// speedup vs baseline: 1.2349x; 1.0471x over previous
#include <cuda_runtime.h>
#include <math.h>

#define B_    8
#define CIN_  512
#define COUT_ 3
#define HW_   65536   // 256*256
#define ZDIM_ 512
#define PRE_  6       // channels prefetched before the PDL dependency sync

// Final demodulated weights, padded float4 per ci: (w0,w1,w2,0). [B][CIN]
__device__ float4 g_ww4[B_ * CIN_];

// ---------------------------------------------------------------------------
// Kernel 1: full style pipeline in one block per batch.
// grid=(B), block=1024 = 128 ci4-lanes (4 ci each) x 8 z-slices (64 z each).
// ---------------------------------------------------------------------------
__global__ __launch_bounds__(1024) void style_kernel(const float* __restrict__ y,
                                                     const float* __restrict__ w,
                                                     const float* __restrict__ dense_w,
                                                     const float* __restrict__ dense_b) {
    const int b    = blockIdx.x;
    const int tid  = threadIdx.x;
    const int ci4  = tid & 127;     // handles ci = ci4*4 .. ci4*4+3
    const int zs   = tid >> 7;      // 0..7, z in [zs*64, zs*64+64)

    __shared__ float  sy[ZDIM_];
    __shared__ float4 sred[8][128];  // [zslice][ci4]
    __shared__ float  swq[4][3];     // per-warp square partials
    __shared__ float  sdq[3];        // final demod sums

    if (tid < ZDIM_) sy[tid] = y[b * ZDIM_ + tid];
    __syncthreads();

    const float4* dw4 = reinterpret_cast<const float4*>(dense_w);
    float4 acc = make_float4(0.f, 0.f, 0.f, 0.f);
    const int z0 = zs * 64;
#pragma unroll 16
    for (int zz = 0; zz < 64; ++zz) {
        const int z = z0 + zz;
        const float  yv = sy[z];
        const float4 dv = dw4[z * 128 + ci4];
        acc.x = fmaf(yv, dv.x, acc.x);
        acc.y = fmaf(yv, dv.y, acc.y);
        acc.z = fmaf(yv, dv.z, acc.z);
        acc.w = fmaf(yv, dv.w, acc.w);
    }
    sred[zs][ci4] = acc;
    __syncthreads();

    float ww[4][3];
    if (tid < 128) {
        float4 dot = sred[0][ci4];
#pragma unroll
        for (int k = 1; k < 8; ++k) {
            const float4 v = sred[k][ci4];
            dot.x += v.x; dot.y += v.y; dot.z += v.z; dot.w += v.w;
        }
        const float rc = 0.044194173824159216f;   // 1/sqrt(512)
        const int   ci0 = ci4 * 4;
        const float s[4] = {
            dot.x * rc + dense_b[ci0 + 0] + 1.0f,
            dot.y * rc + dense_b[ci0 + 1] + 1.0f,
            dot.z * rc + dense_b[ci0 + 2] + 1.0f,
            dot.w * rc + dense_b[ci0 + 3] + 1.0f };

        float q0 = 0.f, q1 = 0.f, q2 = 0.f;
#pragma unroll
        for (int j = 0; j < 4; ++j) {
            const float* wp = w + (ci0 + j) * COUT_;
            ww[j][0] = rc * wp[0] * s[j];
            ww[j][1] = rc * wp[1] * s[j];
            ww[j][2] = rc * wp[2] * s[j];
            q0 += ww[j][0] * ww[j][0];
            q1 += ww[j][1] * ww[j][1];
            q2 += ww[j][2] * ww[j][2];
        }
#pragma unroll
        for (int off = 16; off >= 1; off >>= 1) {
            q0 += __shfl_xor_sync(0xFFFFFFFF, q0, off);
            q1 += __shfl_xor_sync(0xFFFFFFFF, q1, off);
            q2 += __shfl_xor_sync(0xFFFFFFFF, q2, off);
        }
        const int warp = ci4 >> 5;
        if ((ci4 & 31) == 0) {
            swq[warp][0] = q0; swq[warp][1] = q1; swq[warp][2] = q2;
        }
    }
    __syncthreads();
    if (tid < 3)
        sdq[tid] = swq[0][tid] + swq[1][tid] + swq[2][tid] + swq[3][tid];
    __syncthreads();

    if (tid < 128) {
        const float d0 = rsqrtf(sdq[0] + 1e-8f);
        const float d1 = rsqrtf(sdq[1] + 1e-8f);
        const float d2 = rsqrtf(sdq[2] + 1e-8f);
        const int ci0 = ci4 * 4;
#pragma unroll
        for (int j = 0; j < 4; ++j)
            g_ww4[b * CIN_ + ci0 + j] =
                make_float4(ww[j][0] * d0, ww[j][1] * d1, ww[j][2] * d2, 0.f);
    }
}

// ---------------------------------------------------------------------------
// Kernel 2: pointwise conv, HBM streaming. grid=(128, B), block=128.
// PDL: prefetch first PRE_ channels of x (weight-independent) BEFORE the
// grid dependency sync, so the big stream starts while style still runs.
// ---------------------------------------------------------------------------
__global__ __launch_bounds__(128) void conv_kernel(const float* __restrict__ x,
                                                   float* __restrict__ out) {
    const int b    = blockIdx.y;
    const int pix4 = blockIdx.x * 128 + threadIdx.x;  // 0 .. HW/4-1

    const float4* xb = reinterpret_cast<const float4*>(
                           x + (size_t)b * CIN_ * HW_) + pix4;

    // --- weight-independent prefetch (overlaps with style via PDL) ---
    float4 pre[PRE_];
#pragma unroll
    for (int j = 0; j < PRE_; ++j)
        pre[j] = xb[(size_t)j * (HW_ / 4)];

    cudaGridDependencySynchronize();   // wait for style_kernel's g_ww4

    __shared__ float sw0[CIN_], sw1[CIN_], sw2[CIN_];
    for (int i = threadIdx.x; i < CIN_; i += 128) {
        const float4 wv = g_ww4[b * CIN_ + i];
        sw0[i] = wv.x; sw1[i] = wv.y; sw2[i] = wv.z;
    }
    __syncthreads();

    float4 a0 = make_float4(0.f, 0.f, 0.f, 0.f);
    float4 a1 = make_float4(0.f, 0.f, 0.f, 0.f);
    float4 a2 = make_float4(0.f, 0.f, 0.f, 0.f);

#pragma unroll
    for (int j = 0; j < PRE_; ++j) {
        const float4 v = pre[j];
        const float w0 = sw0[j], w1 = sw1[j], w2 = sw2[j];
        a0.x = fmaf(w0, v.x, a0.x); a0.y = fmaf(w0, v.y, a0.y);
        a0.z = fmaf(w0, v.z, a0.z); a0.w = fmaf(w0, v.w, a0.w);
        a1.x = fmaf(w1, v.x, a1.x); a1.y = fmaf(w1, v.y, a1.y);
        a1.z = fmaf(w1, v.z, a1.z); a1.w = fmaf(w1, v.w, a1.w);
        a2.x = fmaf(w2, v.x, a2.x); a2.y = fmaf(w2, v.y, a2.y);
        a2.z = fmaf(w2, v.z, a2.z); a2.w = fmaf(w2, v.w, a2.w);
    }

#pragma unroll 8
    for (int ci = PRE_; ci < CIN_; ++ci) {
        const float4 v  = xb[(size_t)ci * (HW_ / 4)];
        const float  w0 = sw0[ci];
        const float  w1 = sw1[ci];
        const float  w2 = sw2[ci];
        a0.x = fmaf(w0, v.x, a0.x); a0.y = fmaf(w0, v.y, a0.y);
        a0.z = fmaf(w0, v.z, a0.z); a0.w = fmaf(w0, v.w, a0.w);
        a1.x = fmaf(w1, v.x, a1.x); a1.y = fmaf(w1, v.y, a1.y);
        a1.z = fmaf(w1, v.z, a1.z); a1.w = fmaf(w1, v.w, a1.w);
        a2.x = fmaf(w2, v.x, a2.x); a2.y = fmaf(w2, v.y, a2.y);
        a2.z = fmaf(w2, v.z, a2.z); a2.w = fmaf(w2, v.w, a2.w);
    }

    float4* ob = reinterpret_cast<float4*>(out + (size_t)b * COUT_ * HW_);
    ob[0 * (HW_ / 4) + pix4] = a0;
    ob[1 * (HW_ / 4) + pix4] = a1;
    ob[2 * (HW_ / 4) + pix4] = a2;
}

// ---------------------------------------------------------------------------
// Inputs: x, y, w, dense_w, dense_b. Output: float [8,3,256,256]
// ---------------------------------------------------------------------------
extern "C" void kernel_launch(void* const* d_in, const int* in_sizes, int n_in,
                              void* d_out, int out_size) {
    const float* x       = (const float*)d_in[0];
    const float* y       = (const float*)d_in[1];
    const float* w       = (const float*)d_in[2];
    const float* dense_w = (const float*)d_in[3];
    const float* dense_b = (const float*)d_in[4];
    float* out = (float*)d_out;

    style_kernel<<<B_, 1024>>>(y, w, dense_w, dense_b);

    // Conv launched with programmatic dependent launch: it may begin while
    // style is still running; conv waits via cudaGridDependencySynchronize().
    cudaLaunchConfig_t cfg = {};
    cfg.gridDim  = dim3(HW_ / 4 / 128, B_);
    cfg.blockDim = dim3(128);
    cfg.dynamicSmemBytes = 0;
    cfg.stream = 0;
    cudaLaunchAttribute attrs[1];
    attrs[0].id = cudaLaunchAttributeProgrammaticStreamSerialization;
    attrs[0].val.programmaticStreamSerializationAllowed = 1;
    cfg.attrs = attrs;
    cfg.numAttrs = 1;
    cudaLaunchKernelEx(&cfg, conv_kernel, x, out);
}

// round 6
// speedup vs baseline: 1.2353x; 1.0004x over previous
#include <cuda_runtime.h>
#include <math.h>

#define B_    8
#define CIN_  512
#define COUT_ 3
#define HW_   65536   // 256*256
#define ZDIM_ 512
#define GRP_  8       // channels per load batch (MLP_p1 = 8)

// Final demodulated weights, padded float4 per ci: (w0,w1,w2,0). [B][CIN]
__device__ float4 g_ww4[B_ * CIN_];

// ---------------------------------------------------------------------------
// Kernel 1: full style pipeline in one block per batch.
// grid=(B), block=1024 = 128 ci4-lanes (4 ci each) x 8 z-slices (64 z each).
// ---------------------------------------------------------------------------
__global__ __launch_bounds__(1024) void style_kernel(const float* __restrict__ y,
                                                     const float* __restrict__ w,
                                                     const float* __restrict__ dense_w,
                                                     const float* __restrict__ dense_b) {
    // Release the dependent conv launch immediately: conv blocks spin up and
    // prefetch their first x group while we compute the weights.
    cudaTriggerProgrammaticLaunchCompletion();

    const int b    = blockIdx.x;
    const int tid  = threadIdx.x;
    const int ci4  = tid & 127;     // handles ci = ci4*4 .. ci4*4+3
    const int zs   = tid >> 7;      // 0..7, z in [zs*64, zs*64+64)

    __shared__ float  sy[ZDIM_];
    __shared__ float4 sred[8][128];  // [zslice][ci4]
    __shared__ float  swq[4][3];     // per-warp square partials
    __shared__ float  sdq[3];        // final demod sums

    if (tid < ZDIM_) sy[tid] = y[b * ZDIM_ + tid];
    __syncthreads();

    const float4* dw4 = reinterpret_cast<const float4*>(dense_w);
    float4 acc = make_float4(0.f, 0.f, 0.f, 0.f);
    const int z0 = zs * 64;
#pragma unroll 16
    for (int zz = 0; zz < 64; ++zz) {
        const int z = z0 + zz;
        const float  yv = sy[z];
        const float4 dv = dw4[z * 128 + ci4];
        acc.x = fmaf(yv, dv.x, acc.x);
        acc.y = fmaf(yv, dv.y, acc.y);
        acc.z = fmaf(yv, dv.z, acc.z);
        acc.w = fmaf(yv, dv.w, acc.w);
    }
    sred[zs][ci4] = acc;
    __syncthreads();

    float ww[4][3];
    if (tid < 128) {
        float4 dot = sred[0][ci4];
#pragma unroll
        for (int k = 1; k < 8; ++k) {
            const float4 v = sred[k][ci4];
            dot.x += v.x; dot.y += v.y; dot.z += v.z; dot.w += v.w;
        }
        const float rc = 0.044194173824159216f;   // 1/sqrt(512)
        const int   ci0 = ci4 * 4;
        const float s[4] = {
            dot.x * rc + dense_b[ci0 + 0] + 1.0f,
            dot.y * rc + dense_b[ci0 + 1] + 1.0f,
            dot.z * rc + dense_b[ci0 + 2] + 1.0f,
            dot.w * rc + dense_b[ci0 + 3] + 1.0f };

        float q0 = 0.f, q1 = 0.f, q2 = 0.f;
#pragma unroll
        for (int j = 0; j < 4; ++j) {
            const float* wp = w + (ci0 + j) * COUT_;
            ww[j][0] = rc * wp[0] * s[j];
            ww[j][1] = rc * wp[1] * s[j];
            ww[j][2] = rc * wp[2] * s[j];
            q0 += ww[j][0] * ww[j][0];
            q1 += ww[j][1] * ww[j][1];
            q2 += ww[j][2] * ww[j][2];
        }
#pragma unroll
        for (int off = 16; off >= 1; off >>= 1) {
            q0 += __shfl_xor_sync(0xFFFFFFFF, q0, off);
            q1 += __shfl_xor_sync(0xFFFFFFFF, q1, off);
            q2 += __shfl_xor_sync(0xFFFFFFFF, q2, off);
        }
        const int warp = ci4 >> 5;
        if ((ci4 & 31) == 0) {
            swq[warp][0] = q0; swq[warp][1] = q1; swq[warp][2] = q2;
        }
    }
    __syncthreads();
    if (tid < 3)
        sdq[tid] = swq[0][tid] + swq[1][tid] + swq[2][tid] + swq[3][tid];
    __syncthreads();

    if (tid < 128) {
        const float d0 = rsqrtf(sdq[0] + 1e-8f);
        const float d1 = rsqrtf(sdq[1] + 1e-8f);
        const float d2 = rsqrtf(sdq[2] + 1e-8f);
        const int ci0 = ci4 * 4;
#pragma unroll
        for (int j = 0; j < 4; ++j)
            g_ww4[b * CIN_ + ci0 + j] =
                make_float4(ww[j][0] * d0, ww[j][1] * d1, ww[j][2] * d2, 0.f);
    }
}

// ---------------------------------------------------------------------------
// Kernel 2: pointwise conv, HBM streaming. grid=(128, B), block=128.
// Channels processed in batches of GRP_=8: 8 independent LDG.128 issued
// back-to-back (MLP_p1=8), then 96 FMAs. Group 0 prefetched before the PDL
// dependency sync so the x stream starts while style runs.
// ---------------------------------------------------------------------------
__global__ __launch_bounds__(128, 7) void conv_kernel(const float* __restrict__ x,
                                                      float* __restrict__ out) {
    const int b    = blockIdx.y;
    const int pix4 = blockIdx.x * 128 + threadIdx.x;  // 0 .. HW/4-1

    const float4* xb = reinterpret_cast<const float4*>(
                           x + (size_t)b * CIN_ * HW_) + pix4;

    // --- weight-independent prefetch of group 0 (overlaps style via PDL) ---
    float4 buf[GRP_];
#pragma unroll
    for (int j = 0; j < GRP_; ++j)
        buf[j] = xb[(size_t)j * (HW_ / 4)];

    cudaGridDependencySynchronize();   // wait for style_kernel's g_ww4

    __shared__ float sw0[CIN_], sw1[CIN_], sw2[CIN_];
    for (int i = threadIdx.x; i < CIN_; i += 128) {
        const float4 wv = g_ww4[b * CIN_ + i];
        sw0[i] = wv.x; sw1[i] = wv.y; sw2[i] = wv.z;
    }
    __syncthreads();

    float4 a0 = make_float4(0.f, 0.f, 0.f, 0.f);
    float4 a1 = make_float4(0.f, 0.f, 0.f, 0.f);
    float4 a2 = make_float4(0.f, 0.f, 0.f, 0.f);

    for (int g = 0; g < CIN_ / GRP_; ++g) {
        const int ci0 = g * GRP_;
        // consume current batch
#pragma unroll
        for (int j = 0; j < GRP_; ++j) {
            const float4 v  = buf[j];
            const float  w0 = sw0[ci0 + j];
            const float  w1 = sw1[ci0 + j];
            const float  w2 = sw2[ci0 + j];
            a0.x = fmaf(w0, v.x, a0.x); a0.y = fmaf(w0, v.y, a0.y);
            a0.z = fmaf(w0, v.z, a0.z); a0.w = fmaf(w0, v.w, a0.w);
            a1.x = fmaf(w1, v.x, a1.x); a1.y = fmaf(w1, v.y, a1.y);
            a1.z = fmaf(w1, v.z, a1.z); a1.w = fmaf(w1, v.w, a1.w);
            a2.x = fmaf(w2, v.x, a2.x); a2.y = fmaf(w2, v.y, a2.y);
            a2.z = fmaf(w2, v.z, a2.z); a2.w = fmaf(w2, v.w, a2.w);
        }
        // issue next batch of 8 independent loads back-to-back
        if (g + 1 < CIN_ / GRP_) {
            const int cn = ci0 + GRP_;
#pragma unroll
            for (int j = 0; j < GRP_; ++j)
                buf[j] = xb[(size_t)(cn + j) * (HW_ / 4)];
        }
    }

    float4* ob = reinterpret_cast<float4*>(out + (size_t)b * COUT_ * HW_);
    ob[0 * (HW_ / 4) + pix4] = a0;
    ob[1 * (HW_ / 4) + pix4] = a1;
    ob[2 * (HW_ / 4) + pix4] = a2;
}

// ---------------------------------------------------------------------------
// Inputs: x, y, w, dense_w, dense_b. Output: float [8,3,256,256]
// ---------------------------------------------------------------------------
extern "C" void kernel_launch(void* const* d_in, const int* in_sizes, int n_in,
                              void* d_out, int out_size) {
    const float* x       = (const float*)d_in[0];
    const float* y       = (const float*)d_in[1];
    const float* w       = (const float*)d_in[2];
    const float* dense_w = (const float*)d_in[3];
    const float* dense_b = (const float*)d_in[4];
    float* out = (float*)d_out;

    style_kernel<<<B_, 1024>>>(y, w, dense_w, dense_b);

    cudaLaunchConfig_t cfg = {};
    cfg.gridDim  = dim3(HW_ / 4 / 128, B_);
    cfg.blockDim = dim3(128);
    cfg.dynamicSmemBytes = 0;
    cfg.stream = 0;
    cudaLaunchAttribute attrs[1];
    attrs[0].id = cudaLaunchAttributeProgrammaticStreamSerialization;
    attrs[0].val.programmaticStreamSerializationAllowed = 1;
    cfg.attrs = attrs;
    cfg.numAttrs = 1;
    cudaLaunchKernelEx(&cfg, conv_kernel, x, out);
}